// round 9
// baseline (speedup 1.0000x reference)
#include <cuda_runtime.h>
#include <cuda_fp16.h>
#include <cstdint>
#include <cstddef>

#define BATCH 4
#define C_IN 256
#define C_I 128
#define HH 96
#define WW 96
#define HW 9216
#define PH 47
#define M_VALID 2209
#define M_PAD 2240
#define N_MTILES 35        // 2240 / 64
#define TILE_N 128
#define TILE_M 64

// ---------------- scratch (device globals; zero-initialized) ----------------
__device__ uint16_t d_xH[(size_t)BATCH * HW * C_IN];        // [b][hw][c] half
__device__ uint16_t d_convH[(size_t)3 * BATCH * C_I * HW];  // [g|th|phi][b][ci][hw]
__device__ uint16_t d_phiH[(size_t)BATCH * M_PAD * C_I];    // [b][m][ci]
__device__ uint16_t d_gH[(size_t)BATCH * C_I * M_PAD];      // [b][ci][m]
__device__ uint16_t d_yH[(size_t)BATCH * HW * C_I];         // [b][n][ci]

// ---------------- helpers ----------------------------------------------------
__device__ __forceinline__ uint32_t pkh2(float a, float b) {
    __half2 h = __floats2half2_rn(a, b);
    return *(uint32_t*)&h;
}
__device__ __forceinline__ uint32_t pku16(uint16_t a, uint16_t b) {
    return (uint32_t)a | ((uint32_t)b << 16);
}
__device__ __forceinline__ void mma_f16(float* d, const uint32_t* a,
                                        uint32_t b0, uint32_t b1) {
    asm volatile(
        "mma.sync.aligned.m16n8k16.row.col.f32.f16.f16.f32 "
        "{%0,%1,%2,%3}, {%4,%5,%6,%7}, {%8,%9}, {%0,%1,%2,%3};"
        : "+f"(d[0]), "+f"(d[1]), "+f"(d[2]), "+f"(d[3])
        : "r"(a[0]), "r"(a[1]), "r"(a[2]), "r"(a[3]), "r"(b0), "r"(b1));
}
#define BAR_SYNC(id, cnt) \
    asm volatile("bar.sync %0, %1;" :: "r"(id), "r"(cnt) : "memory")
#define BAR_ARRIVE(id, cnt) \
    asm volatile("bar.arrive %0, %1;" :: "r"(id), "r"(cnt) : "memory")

// ---------------- kernel 0: transpose x -> [b][hw][c] half ------------------
__global__ __launch_bounds__(256) void k_xpose(const float* __restrict__ x)
{
    __shared__ float tile[32][33];
    const int hw0 = blockIdx.x * 32;
    const int c0  = blockIdx.y * 32;
    const int b   = blockIdx.z;
    const int tx  = threadIdx.x & 31;
    const int ty  = threadIdx.x >> 5;   // 0..7
    const float* xb = x + ((size_t)b * C_IN + c0) * HW + hw0;
#pragma unroll
    for (int j = 0; j < 4; ++j)
        tile[ty + j * 8][tx] = xb[(size_t)(ty + j * 8) * HW + tx];
    __syncthreads();
    uint16_t* ob = d_xH + ((size_t)b * HW + hw0) * C_IN + c0;
#pragma unroll
    for (int j = 0; j < 4; ++j)
        ob[(size_t)(ty + j * 8) * C_IN + tx] =
            __half_as_ushort(__float2half_rn(tile[tx][ty + j * 8]));
}

// ---------------- kernel 1: fused g/theta/phi conv, fp16 mma ----------------
// grid (72, 3, 4). CTA 256 thr / 8 warps; warp tile 32 rows x 64 cols.
// K = 256 in 4 chunks of 64. Ws/Xs: [128][36] uint32 words (packed half2).
__global__ __launch_bounds__(256, 2) void k_conv3(
    const float* __restrict__ gw, const float* __restrict__ gb,
    const float* __restrict__ tw, const float* __restrict__ tb,
    const float* __restrict__ pw, const float* __restrict__ pb)
{
    __shared__ uint32_t Ws[128 * 36];
    __shared__ uint32_t Xs[128 * 36];

    const int t    = threadIdx.x;
    const int w    = t >> 5;
    const int lane = t & 31;
    const int g    = lane >> 2;
    const int tg   = lane & 3;
    const int rw   = (w & 3) * 32;
    const int cw   = (w >> 2) * 64;
    const int n0   = blockIdx.x * 128;
    const int head = blockIdx.y;
    const int b    = blockIdx.z;
    const float* Wp = (head == 0) ? gw : (head == 1 ? tw : pw);
    const float* Bp = (head == 0) ? gb : (head == 1 ? tb : pb);
    const uint16_t* xb = d_xH + (size_t)b * HW * C_IN + (size_t)n0 * C_IN;

    float o[2][8][4];
#pragma unroll
    for (int rt = 0; rt < 2; ++rt)
#pragma unroll
        for (int nt = 0; nt < 8; ++nt) {
            o[rt][nt][0] = 0.f; o[rt][nt][1] = 0.f;
            o[rt][nt][2] = 0.f; o[rt][nt][3] = 0.f;
        }

    for (int k0 = 0; k0 < 256; k0 += 64) {
        __syncthreads();
        // W chunk: 128 rows x 64 k (fp32 -> packed half2)
        {
            const int r = t & 127;
#pragma unroll
            for (int it = 0; it < 8; ++it) {
                int cu = (t >> 7) + it * 2;          // 0..15
                float4 v = *(const float4*)(Wp + (size_t)r * 256 + k0 + cu * 4);
                *(uint2*)(Ws + r * 36 + cu * 2) =
                    make_uint2(pkh2(v.x, v.y), pkh2(v.z, v.w));
            }
        }
        // X chunk: 128 n x 64 k halves, direct uint4 from [n][k] gmem
        {
            const int r = t & 127;
#pragma unroll
            for (int it = 0; it < 4; ++it) {
                int c8 = (t >> 7) + it * 2;          // 0..7
                uint4 v = *(const uint4*)(xb + (size_t)r * C_IN + k0 + c8 * 8);
                *(uint4*)(Xs + r * 36 + c8 * 4) = v;
            }
        }
        __syncthreads();
#pragma unroll
        for (int ks = 0; ks < 4; ++ks) {
            uint32_t a[2][4];
#pragma unroll
            for (int rt = 0; rt < 2; ++rt) {
                int rb = rw + rt * 16 + g;
                a[rt][0] = Ws[rb * 36 + ks * 8 + tg];
                a[rt][1] = Ws[(rb + 8) * 36 + ks * 8 + tg];
                a[rt][2] = Ws[rb * 36 + ks * 8 + tg + 4];
                a[rt][3] = Ws[(rb + 8) * 36 + ks * 8 + tg + 4];
            }
#pragma unroll
            for (int nt = 0; nt < 8; ++nt) {
                uint32_t b0 = Xs[(cw + nt * 8 + g) * 36 + ks * 8 + tg];
                uint32_t b1 = Xs[(cw + nt * 8 + g) * 36 + ks * 8 + tg + 4];
                mma_f16(o[0][nt], a[0], b0, b1);
                mma_f16(o[1][nt], a[1], b0, b1);
            }
        }
    }
    uint16_t* outp = d_convH + ((size_t)(head * BATCH + b) * C_I) * HW;
#pragma unroll
    for (int rt = 0; rt < 2; ++rt) {
        int r0 = rw + rt * 16 + g;
        float bi0 = Bp[r0], bi1 = Bp[r0 + 8];
#pragma unroll
        for (int nt = 0; nt < 8; ++nt) {
            int col = n0 + cw + nt * 8 + 2 * tg;
            *(uint32_t*)(outp + (size_t)r0 * HW + col) =
                pkh2(o[rt][nt][0] + bi0, o[rt][nt][1] + bi0);
            *(uint32_t*)(outp + (size_t)(r0 + 8) * HW + col) =
                pkh2(o[rt][nt][2] + bi1, o[rt][nt][3] + bi1);
        }
    }
}

// ---------------- kernel 2: 3x3/2 maxpool (half in/out) ---------------------
__global__ void k_pool()
{
    int idx = blockIdx.x * blockDim.x + threadIdx.x;
    const int total = 2 * BATCH * C_I * M_VALID;
    if (idx >= total) return;
    int m = idx % M_VALID; int r1 = idx / M_VALID;
    int o = r1 % C_I;      int r2 = r1 / C_I;
    int b = r2 % BATCH;    int which = r2 / BATCH;   // 0 = g, 1 = phi
    int slot = which ? 2 : 0;
    const uint16_t* src = d_convH + ((size_t)(slot * BATCH + b) * C_I + o) * HW;
    int pr = m / PH, pc = m % PH;
    const uint16_t* p = src + (pr * 2) * WW + pc * 2;
    float v = __half2float(__ushort_as_half(p[0]));
#pragma unroll
    for (int dy = 0; dy < 3; ++dy)
#pragma unroll
        for (int dx = 0; dx < 3; ++dx) {
            if (dy == 0 && dx == 0) continue;
            v = fmaxf(v, __half2float(__ushort_as_half(p[dy * WW + dx])));
        }
    uint16_t h = __half_as_ushort(__float2half_rn(v));
    if (which == 0) d_gH[((size_t)b * C_I + o) * M_PAD + m] = h;
    else            d_phiH[((size_t)b * M_PAD + m) * C_I + o] = h;
}

// ---------------- kernel 3: warp-specialized fp16 flash attention -----------
#define PHI_OFS(s) ((s) * 4352)
#define G_OFS(s)   (8704 + (s) * 8704)
#define P_OFS(s)   (26112 + (s) * 4608)
#define A_OFS(s)   (35328 + (s) * 128)
#define L_OFS      35584
#define ATTN_SMEM_BYTES ((35584 + 128) * 4)
#define B_PROD  1
#define B_CONS  2
#define B_PRDY(s)  (3 + (s))
#define B_PFREE(s) (5 + (s))

__global__ __launch_bounds__(256, 1) void k_attn()
{
    extern __shared__ uint32_t sm[];
    float* smf = (float*)sm;
    const int t    = threadIdx.x;
    const int w    = t >> 5;
    const int lane = t & 31;
    const int g    = lane >> 2;
    const int tg   = lane & 3;
    const int b    = blockIdx.y;
    const int n0   = blockIdx.x * TILE_N;

    if (w < 4) {
        // ================= PRODUCERS: MMA1 + softmax =========================
        const int ptid = t;
        const int rw   = w * 32;
        uint32_t aF[2][8][4];
        {
            const uint16_t* thp =
                d_convH + ((size_t)(1 * BATCH + b) * C_I) * HW + n0 + rw;
#pragma unroll
            for (int mt = 0; mt < 2; ++mt) {
                const int nlo = mt * 16 + g;
#pragma unroll
                for (int kc = 0; kc < 8; ++kc) {
                    const uint16_t* c0 = thp + (size_t)(kc * 16 + 2 * tg) * HW;
                    const uint16_t* c1 = c0 + HW;
                    const uint16_t* c2 = thp + (size_t)(kc * 16 + 2 * tg + 8) * HW;
                    const uint16_t* c3 = c2 + HW;
                    aF[mt][kc][0] = pku16(c0[nlo], c1[nlo]);
                    aF[mt][kc][1] = pku16(c0[nlo + 8], c1[nlo + 8]);
                    aF[mt][kc][2] = pku16(c2[nlo], c3[nlo]);
                    aF[mt][kc][3] = pku16(c2[nlo + 8], c3[nlo + 8]);
                }
            }
        }
        const uint16_t* psrc = d_phiH + (size_t)b * M_PAD * C_I;
        {
#pragma unroll
            for (int it = 0; it < 8; ++it) {
                int f4 = ptid + it * 128;
                int r = f4 >> 4, c8 = f4 & 15;
                uint4 v = *(const uint4*)(psrc + (size_t)r * C_I + c8 * 8);
                *(uint4*)(sm + PHI_OFS(0) + r * 68 + c8 * 4) = v;
            }
        }
        BAR_SYNC(B_PROD, 128);

        float mrun[2][2], lA[2][2];
#pragma unroll
        for (int mt = 0; mt < 2; ++mt) {
            mrun[mt][0] = -1e30f; mrun[mt][1] = -1e30f;
            lA[mt][0] = 0.f; lA[mt][1] = 0.f;
        }

        for (int mt_i = 0; mt_i < N_MTILES; ++mt_i) {
            const int s = mt_i & 1;
            if (mt_i + 1 < N_MTILES) {
                const int m1 = (mt_i + 1) * TILE_M;
#pragma unroll
                for (int it = 0; it < 8; ++it) {
                    int f4 = ptid + it * 128;
                    int r = f4 >> 4, c8 = f4 & 15;
                    uint4 v = *(const uint4*)(psrc + (size_t)(m1 + r) * C_I + c8 * 8);
                    *(uint4*)(sm + PHI_OFS(1 - s) + r * 68 + c8 * 4) = v;
                }
            }
            const uint32_t* phi_s = sm + PHI_OFS(s);
            float sA[2][8][4];
#pragma unroll
            for (int mt = 0; mt < 2; ++mt)
#pragma unroll
                for (int j = 0; j < 8; ++j) {
                    sA[mt][j][0] = 0.f; sA[mt][j][1] = 0.f;
                    sA[mt][j][2] = 0.f; sA[mt][j][3] = 0.f;
                }
#pragma unroll
            for (int kc = 0; kc < 8; ++kc)
#pragma unroll
                for (int j = 0; j < 8; ++j) {
                    uint32_t b0 = phi_s[(j * 8 + g) * 68 + kc * 8 + tg];
                    uint32_t b1 = phi_s[(j * 8 + g) * 68 + kc * 8 + tg + 4];
                    mma_f16(sA[0][j], aF[0][kc], b0, b1);
                    mma_f16(sA[1][j], aF[1][kc], b0, b1);
                }
            float al[2][2];
#pragma unroll
            for (int mt = 0; mt < 2; ++mt) {
                float mx0 = sA[mt][0][0], mx1 = sA[mt][0][2];
#pragma unroll
                for (int j = 0; j < 8; ++j) {
                    mx0 = fmaxf(mx0, fmaxf(sA[mt][j][0], sA[mt][j][1]));
                    mx1 = fmaxf(mx1, fmaxf(sA[mt][j][2], sA[mt][j][3]));
                }
                mx0 = fmaxf(mx0, __shfl_xor_sync(0xffffffffu, mx0, 1));
                mx0 = fmaxf(mx0, __shfl_xor_sync(0xffffffffu, mx0, 2));
                mx1 = fmaxf(mx1, __shfl_xor_sync(0xffffffffu, mx1, 1));
                mx1 = fmaxf(mx1, __shfl_xor_sync(0xffffffffu, mx1, 2));
                if (mx0 > mrun[mt][0]) {
                    al[mt][0] = __expf(mrun[mt][0] - mx0); mrun[mt][0] = mx0;
                } else al[mt][0] = 1.f;
                if (mx1 > mrun[mt][1]) {
                    al[mt][1] = __expf(mrun[mt][1] - mx1); mrun[mt][1] = mx1;
                } else al[mt][1] = 1.f;
                lA[mt][0] *= al[mt][0];
                lA[mt][1] *= al[mt][1];
            }
            if (mt_i >= 2) BAR_SYNC(B_PFREE(s), 256);
            if (tg == 0) {
#pragma unroll
                for (int mt = 0; mt < 2; ++mt) {
                    smf[A_OFS(s) + rw + mt * 16 + g]     = al[mt][0];
                    smf[A_OFS(s) + rw + mt * 16 + g + 8] = al[mt][1];
                }
            }
            uint32_t* p_s = sm + P_OFS(s);
            const int m0 = mt_i * TILE_M;
            const bool lastt = (mt_i == N_MTILES - 1);
#pragma unroll
            for (int mt = 0; mt < 2; ++mt) {
                const int row = rw + mt * 16;
#pragma unroll
                for (int j = 0; j < 8; ++j) {
                    float e00 = __expf(sA[mt][j][0] - mrun[mt][0]);
                    float e01 = __expf(sA[mt][j][1] - mrun[mt][0]);
                    float e10 = __expf(sA[mt][j][2] - mrun[mt][1]);
                    float e11 = __expf(sA[mt][j][3] - mrun[mt][1]);
                    if (lastt) {
                        int mcol = m0 + j * 8 + 2 * tg;
                        if (mcol >= M_VALID)     { e00 = 0.f; e10 = 0.f; }
                        if (mcol + 1 >= M_VALID) { e01 = 0.f; e11 = 0.f; }
                    }
                    lA[mt][0] += e00 + e01;
                    lA[mt][1] += e10 + e11;
                    p_s[(row + g) * 36 + j * 4 + tg] =
                        pkh2(e00 * 256.f, e01 * 256.f);
                    p_s[(row + g + 8) * 36 + j * 4 + tg] =
                        pkh2(e10 * 256.f, e11 * 256.f);
                }
            }
            if (lastt) {
#pragma unroll
                for (int mt = 0; mt < 2; ++mt)
#pragma unroll
                    for (int h = 0; h < 2; ++h) {
                        lA[mt][h] += __shfl_xor_sync(0xffffffffu, lA[mt][h], 1);
                        lA[mt][h] += __shfl_xor_sync(0xffffffffu, lA[mt][h], 2);
                    }
                if (tg == 0) {
#pragma unroll
                    for (int mt = 0; mt < 2; ++mt) {
                        smf[L_OFS + rw + mt * 16 + g]     = lA[mt][0];
                        smf[L_OFS + rw + mt * 16 + g + 8] = lA[mt][1];
                    }
                }
            }
            BAR_ARRIVE(B_PRDY(s), 256);
            BAR_SYNC(B_PROD, 128);
        }
    } else {
        // ================= CONSUMERS: MMA2 ===================================
        const int ctid = t - 128;
        const int w2   = w - 4;
        const int rw2  = w2 * 32;
        const uint16_t* gsrc = d_gH + (size_t)b * C_I * M_PAD;
        {
#pragma unroll
            for (int it = 0; it < 8; ++it) {
                int f4 = ctid + it * 128;
                int r = f4 >> 3, c8 = f4 & 7;
                uint4 v = *(const uint4*)(gsrc + (size_t)r * M_PAD + c8 * 8);
                *(uint4*)(sm + G_OFS(0) + r * 68 + c8 * 4) = v;
            }
        }
        BAR_SYNC(B_CONS, 128);

        float oA[2][16][4];
#pragma unroll
        for (int mt = 0; mt < 2; ++mt)
#pragma unroll
            for (int dt = 0; dt < 16; ++dt) {
                oA[mt][dt][0] = 0.f; oA[mt][dt][1] = 0.f;
                oA[mt][dt][2] = 0.f; oA[mt][dt][3] = 0.f;
            }

        for (int mt_i = 0; mt_i < N_MTILES; ++mt_i) {
            const int s = mt_i & 1;
            if (mt_i + 1 < N_MTILES) {
                const int m1 = (mt_i + 1) * TILE_M;
#pragma unroll
                for (int it = 0; it < 8; ++it) {
                    int f4 = ctid + it * 128;
                    int r = f4 >> 3, c8 = f4 & 7;
                    uint4 v = *(const uint4*)(gsrc + (size_t)r * M_PAD + m1 + c8 * 8);
                    *(uint4*)(sm + G_OFS(1 - s) + r * 68 + c8 * 4) = v;
                }
            }
            BAR_SYNC(B_PRDY(s), 256);
            {
                float a00 = smf[A_OFS(s) + rw2 + g];
                float a01 = smf[A_OFS(s) + rw2 + g + 8];
                float a10 = smf[A_OFS(s) + rw2 + 16 + g];
                float a11 = smf[A_OFS(s) + rw2 + 16 + g + 8];
                float mn = fminf(fminf(a00, a01), fminf(a10, a11));
                if (__any_sync(0xffffffffu, mn < 1.f)) {
#pragma unroll
                    for (int dt = 0; dt < 16; ++dt) {
                        oA[0][dt][0] *= a00; oA[0][dt][1] *= a00;
                        oA[0][dt][2] *= a01; oA[0][dt][3] *= a01;
                        oA[1][dt][0] *= a10; oA[1][dt][1] *= a10;
                        oA[1][dt][2] *= a11; oA[1][dt][3] *= a11;
                    }
                }
            }
            const uint32_t* g_s = sm + G_OFS(s);
            const uint32_t* p_s = sm + P_OFS(s);
#pragma unroll
            for (int kc2 = 0; kc2 < 4; ++kc2) {
                uint32_t pa[2][4];
#pragma unroll
                for (int mt = 0; mt < 2; ++mt) {
                    const int row = rw2 + mt * 16;
                    pa[mt][0] = p_s[(row + g) * 36 + kc2 * 8 + tg];
                    pa[mt][1] = p_s[(row + g + 8) * 36 + kc2 * 8 + tg];
                    pa[mt][2] = p_s[(row + g) * 36 + kc2 * 8 + tg + 4];
                    pa[mt][3] = p_s[(row + g + 8) * 36 + kc2 * 8 + tg + 4];
                }
#pragma unroll
                for (int dt = 0; dt < 16; ++dt) {
                    uint32_t b0 = g_s[(dt * 8 + g) * 68 + kc2 * 8 + tg];
                    uint32_t b1 = g_s[(dt * 8 + g) * 68 + kc2 * 8 + tg + 4];
                    mma_f16(oA[0][dt], pa[0], b0, b1);
                    mma_f16(oA[1][dt], pa[1], b0, b1);
                }
            }
            BAR_ARRIVE(B_PFREE(s), 256);
            BAR_SYNC(B_CONS, 128);
        }

        // finalize: read l, normalize (incl. x256 P scale), store y half
#pragma unroll
        for (int mt = 0; mt < 2; ++mt) {
            const float l0 = smf[L_OFS + rw2 + mt * 16 + g];
            const float l1 = smf[L_OFS + rw2 + mt * 16 + g + 8];
            const float inv0 = 1.0f / (256.f * l0);
            const float inv1 = 1.0f / (256.f * l1);
            uint16_t* yr0 = d_yH + ((size_t)b * HW + n0 + rw2 + mt * 16 + g) * C_I;
            uint16_t* yr1 = yr0 + (size_t)8 * C_I;
#pragma unroll
            for (int dt = 0; dt < 16; ++dt) {
                *(uint32_t*)(yr0 + dt * 8 + 2 * tg) =
                    pkh2(oA[mt][dt][0] * inv0, oA[mt][dt][1] * inv0);
                *(uint32_t*)(yr1 + dt * 8 + 2 * tg) =
                    pkh2(oA[mt][dt][2] * inv1, oA[mt][dt][3] * inv1);
            }
        }
    }
}

// ---------------- kernel 4: W_y conv fp16 mma + bias + residual -------------
// grid (72, 2, 4): x = 128-col tile, y = 128-row out-ch tile, z = batch.
__global__ __launch_bounds__(256, 2) void k_out(
    const float* __restrict__ ww, const float* __restrict__ wb,
    const float* __restrict__ x, float* __restrict__ out)
{
    __shared__ uint32_t Ws[128 * 36];
    __shared__ uint32_t Ys[128 * 36];

    const int t    = threadIdx.x;
    const int w    = t >> 5;
    const int lane = t & 31;
    const int g    = lane >> 2;
    const int tg   = lane & 3;
    const int rw   = (w & 3) * 32;
    const int cw   = (w >> 2) * 64;
    const int n0   = blockIdx.x * 128;
    const int row0 = blockIdx.y * 128;
    const int b    = blockIdx.z;
    const uint16_t* yb = d_yH + (size_t)b * HW * C_I + (size_t)n0 * C_I;

    float o[2][8][4];
#pragma unroll
    for (int rt = 0; rt < 2; ++rt)
#pragma unroll
        for (int nt = 0; nt < 8; ++nt) {
            o[rt][nt][0] = 0.f; o[rt][nt][1] = 0.f;
            o[rt][nt][2] = 0.f; o[rt][nt][3] = 0.f;
        }

    for (int k0 = 0; k0 < 128; k0 += 64) {
        __syncthreads();
        {
            const int r = t & 127;
#pragma unroll
            for (int it = 0; it < 8; ++it) {
                int cu = (t >> 7) + it * 2;          // 0..15
                float4 v = *(const float4*)(ww + (size_t)(row0 + r) * C_I + k0 + cu * 4);
                *(uint2*)(Ws + r * 36 + cu * 2) =
                    make_uint2(pkh2(v.x, v.y), pkh2(v.z, v.w));
            }
        }
        {
            const int r = t & 127;
#pragma unroll
            for (int it = 0; it < 4; ++it) {
                int c8 = (t >> 7) + it * 2;          // 0..7
                uint4 v = *(const uint4*)(yb + (size_t)r * C_I + k0 + c8 * 8);
                *(uint4*)(Ys + r * 36 + c8 * 4) = v;
            }
        }
        __syncthreads();
#pragma unroll
        for (int ks = 0; ks < 4; ++ks) {
            uint32_t a[2][4];
#pragma unroll
            for (int rt = 0; rt < 2; ++rt) {
                int rb = rw + rt * 16 + g;
                a[rt][0] = Ws[rb * 36 + ks * 8 + tg];
                a[rt][1] = Ws[(rb + 8) * 36 + ks * 8 + tg];
                a[rt][2] = Ws[rb * 36 + ks * 8 + tg + 4];
                a[rt][3] = Ws[(rb + 8) * 36 + ks * 8 + tg + 4];
            }
#pragma unroll
            for (int nt = 0; nt < 8; ++nt) {
                uint32_t b0 = Ys[(cw + nt * 8 + g) * 36 + ks * 8 + tg];
                uint32_t b1 = Ys[(cw + nt * 8 + g) * 36 + ks * 8 + tg + 4];
                mma_f16(o[0][nt], a[0], b0, b1);
                mma_f16(o[1][nt], a[1], b0, b1);
            }
        }
    }
#pragma unroll
    for (int rt = 0; rt < 2; ++rt) {
        int r0 = row0 + rw + rt * 16 + g;
        float bi0 = wb[r0], bi1 = wb[r0 + 8];
        const float* x0 = x + ((size_t)b * C_IN + r0) * HW + n0;
        const float* x1 = x + ((size_t)b * C_IN + r0 + 8) * HW + n0;
        float* o0 = out + ((size_t)b * C_IN + r0) * HW + n0;
        float* o1 = out + ((size_t)b * C_IN + r0 + 8) * HW + n0;
#pragma unroll
        for (int nt = 0; nt < 8; ++nt) {
            int col = cw + nt * 8 + 2 * tg;
            float2 xv0 = *(const float2*)(x0 + col);
            float2 xv1 = *(const float2*)(x1 + col);
            *(float2*)(o0 + col) = make_float2(o[rt][nt][0] + bi0 + xv0.x,
                                               o[rt][nt][1] + bi0 + xv0.y);
            *(float2*)(o1 + col) = make_float2(o[rt][nt][2] + bi1 + xv1.x,
                                               o[rt][nt][3] + bi1 + xv1.y);
        }
    }
}

// ---------------- launch ----------------------------------------------------
extern "C" void kernel_launch(void* const* d_in, const int* in_sizes, int n_in,
                              void* d_out, int out_size)
{
    const float* x  = (const float*)d_in[0];
    const float* gw = (const float*)d_in[1];
    const float* gb = (const float*)d_in[2];
    const float* tw = (const float*)d_in[3];
    const float* tb = (const float*)d_in[4];
    const float* pw = (const float*)d_in[5];
    const float* pb = (const float*)d_in[6];
    const float* ww = (const float*)d_in[7];
    const float* wb = (const float*)d_in[8];
    float* out = (float*)d_out;

    cudaFuncSetAttribute(k_attn, cudaFuncAttributeMaxDynamicSharedMemorySize,
                         ATTN_SMEM_BYTES);

    k_xpose<<<dim3(HW / 32, C_IN / 32, BATCH), 256>>>(x);
    k_conv3<<<dim3(HW / 128, 3, BATCH), 256>>>(gw, gb, tw, tb, pw, pb);
    const int pool_total = 2 * BATCH * C_I * M_VALID;
    k_pool<<<(pool_total + 255) / 256, 256>>>();
    k_attn<<<dim3(HW / TILE_N, BATCH), 256, ATTN_SMEM_BYTES>>>();
    k_out<<<dim3(HW / 128, C_IN / 128, BATCH), 256>>>(ww, wb, x, out);
}